// round 10
// baseline (speedup 1.0000x reference)
#include <cuda_runtime.h>
#include <math.h>

#define Bn 128
#define Cn 48
#define Hn 64
#define Wn 64
#define Pn 32
#define OUT_ELEMS (Bn*Cn*Hn*Wn)

// Scratch (no allocations allowed)
__device__ unsigned long long g_M2[Cn*Cn];   // M duplicated (m,m) as f32x2
__device__ float4 g_Spart[1024];             // partials: idx = (b*2+g)*4 + kq

#define FMA2(acc, mm, vv) asm("fma.rn.f32x2 %0, %1, %2, %0;" : "+l"(acc) : "l"(mm), "l"(vv))
#define PACK2(dst, lo, hi) asm("mov.b64 %0, {%1,%2};" : "=l"(dst) : "f"(lo), "f"(hi))
#define UNPACK2(lo, hi, src) asm("mov.b64 {%0,%1}, %2;" : "=f"(lo), "=f"(hi) : "l"(src))

// ---------------------------------------------------------------------------
// Kernel A: prep. 9 blocks x 256 threads, smem-staged W, 1 output/thread.
// ---------------------------------------------------------------------------
__global__ __launch_bounds__(256) void prep_kernel(
        const float* __restrict__ Wq1, const float* __restrict__ Wq2,
        const float* __restrict__ Wq3, const float* __restrict__ Wk1,
        const float* __restrict__ Wk2, const float* __restrict__ Wk3) {
    __shared__ float sW[6][Cn*Cn];   // 55296 B

    const int tid = threadIdx.x;
    const float* Ws[6] = {Wq1, Wk1, Wq2, Wk2, Wq3, Wk3};
    #pragma unroll
    for (int m = 0; m < 6; ++m)
        for (int i = tid; i < Cn*Cn; i += 256) sW[m][i] = Ws[m][i];
    __syncthreads();

    int w = blockIdx.x * 256 + tid;          // 0..2303
    int c = w / Cn, c2 = w % Cn;
    float s = 0.f;
    #pragma unroll
    for (int o = 0; o < Cn; ++o) {
        s += sW[0][o*Cn+c]*sW[1][o*Cn+c2]
           + sW[2][o*Cn+c]*sW[3][o*Cn+c2]
           + sW[4][o*Cn+c]*sW[5][o*Cn+c2];
    }
    s *= (1.0f / sqrtf((float)(Cn*Pn*Pn)));
    ((float2*)g_M2)[w] = make_float2(s, s);
}

// ---------------------------------------------------------------------------
// Kernel B: scores — EXACT R6 form (measured-good). Grid 1024:
// bid -> (b, g, k-quarter kq). Block 256 = 8 warps.
// ---------------------------------------------------------------------------
__global__ __launch_bounds__(256, 3) void score_kernel(const float* __restrict__ x) {
    __shared__ unsigned long long sV[Cn*128];   // 49152 B  [c][k]
    __shared__ unsigned long long sM2[Cn*Cn];   // 18432 B
    __shared__ float4 sred[8];

    const int bid = blockIdx.x;
    const int kq = bid & 3;            // k-quarter (8 y-rows)
    const int g  = (bid >> 2) & 1;     // column-parity group
    const int b  = bid >> 3;
    const int tid = threadIdx.x;

    for (int i = tid; i < Cn*Cn; i += 256) sM2[i] = g_M2[i];

    const float2* xb2 = (const float2*)(x + (size_t)b * Cn * Hn * Wn);

    for (int idx = tid; idx < Cn*128; idx += 256) {
        int c2 = idx >> 7;
        int k  = idx & 127;
        int yy = k >> 4;
        int xx = k & 15;
        int yt = kq*8 + yy;
        float2 a  = xb2[((size_t)c2*Hn + yt)*32      + g*16 + xx];
        float2 bb = xb2[((size_t)c2*Hn + yt + 32)*32 + g*16 + xx];
        unsigned long long pk;
        if (g == 0) PACK2(pk, a.x, bb.x);
        else        PACK2(pk, a.y, bb.y);
        sV[idx] = pk;
    }
    __syncthreads();

    const int ci = tid >> 5;           // warp id: M-row group
    const int kl = tid & 31;           // k lane

    unsigned long long acc[24];
    #pragma unroll
    for (int i = 0; i < 24; ++i) acc[i] = 0ULL;

    #pragma unroll
    for (int c2 = 0; c2 < Cn; ++c2) {
        unsigned long long v0 = sV[c2*128 + kl];
        unsigned long long v1 = sV[c2*128 + kl + 32];
        unsigned long long v2 = sV[c2*128 + kl + 64];
        unsigned long long v3 = sV[c2*128 + kl + 96];
        #pragma unroll
        for (int r = 0; r < 6; ++r) {
            unsigned long long m = sM2[(ci*6 + r)*Cn + c2];   // broadcast
            FMA2(acc[r*4    ], m, v0);
            FMA2(acc[r*4 + 1], m, v1);
            FMA2(acc[r*4 + 2], m, v2);
            FMA2(acc[r*4 + 3], m, v3);
        }
    }

    float p00 = 0.f, p01 = 0.f, p10 = 0.f, p11 = 0.f;
    #pragma unroll
    for (int r = 0; r < 6; ++r) {
        #pragma unroll
        for (int j = 0; j < 4; ++j) {
            float wt, wb, vt, vb;
            UNPACK2(wt, wb, acc[r*4 + j]);
            unsigned long long v = sV[(ci*6 + r)*128 + kl + j*32];
            UNPACK2(vt, vb, v);
            p00 = fmaf(vt, wt, p00);  p01 = fmaf(vt, wb, p01);
            p10 = fmaf(vb, wt, p10);  p11 = fmaf(vb, wb, p11);
        }
    }

    #pragma unroll
    for (int off = 16; off; off >>= 1) {
        p00 += __shfl_xor_sync(0xffffffffu, p00, off);
        p01 += __shfl_xor_sync(0xffffffffu, p01, off);
        p10 += __shfl_xor_sync(0xffffffffu, p10, off);
        p11 += __shfl_xor_sync(0xffffffffu, p11, off);
    }
    if (kl == 0) sred[ci] = make_float4(p00, p01, p10, p11);
    __syncthreads();
    if (tid == 0) {
        float4 sv = sred[0];
        #pragma unroll
        for (int w = 1; w < 8; ++w) {
            float4 t = sred[w];
            sv.x += t.x; sv.y += t.y; sv.z += t.z; sv.w += t.w;
        }
        g_Spart[(b*2+g)*4 + kq] = sv;
    }
}

// ---------------------------------------------------------------------------
// Kernel C: output assembly with FUSED attn (softmax coeffs + logdet).
// x loads issued before the coeff head so it hides under memory latency.
// __stwt stores + reversed batch order (both measured-best in R9).
// ---------------------------------------------------------------------------
__global__ __launch_bounds__(256) void out_kernel(const float* __restrict__ x,
                                                  const float* __restrict__ logdet_in,
                                                  const float* __restrict__ off1p,
                                                  const float* __restrict__ off2p,
                                                  const float* __restrict__ off3p,
                                                  float* __restrict__ out, int out_size) {
    __shared__ float sc[2][4];
    __shared__ float sld[2];

    const int tid = threadIdx.x;
    const int blk = blockIdx.x;
    const int r = blk >> 1;            // r = (127-b)*48 + c, constant per block
    const int b = Bn - 1 - (r / Cn);   // reversed batch order
    const int c = r % Cn;

    // issue main loads first (independent of the coeffs)
    int t  = blk * 256 + tid;
    int x4 = t & 15;
    int y  = (t >> 4) & 31;
    int g  = x4 >> 3;
    size_t base = (((size_t)b*Cn + c)*Hn + y)*Wn + x4*4;
    float4 xt = *(const float4*)(x + base);
    float4 xb = *(const float4*)(x + base + 32*Wn);

    if (tid < 2) {
        int gg = tid;
        const float off  = off1p[0];
        const float off2 = off2p[0];
        const float off3 = off3p[0];
        float4 s = g_Spart[(b*2+gg)*4 + 0];
        #pragma unroll
        for (int qq = 1; qq < 4; ++qq) {
            float4 tt = g_Spart[(b*2+gg)*4 + qq];
            s.x += tt.x; s.y += tt.y; s.z += tt.z; s.w += tt.w;
        }
        float stt = s.x + off3, stb = s.y + off3;
        float sbt = s.z + off3, sbb = s.w + off3;
        float z = off3;

        float mx  = fmaxf(fmaxf(stt, stb), z);
        float e0  = expf(stt-mx), e1 = expf(stb-mx), ez = expf(z-mx);
        float inv = 1.f / (e0 + e1 + 2.f*ez);
        float a_tt = e0*inv + off2 + off;
        float a_tb = e1*inv + off2;

        mx  = fmaxf(fmaxf(sbt, sbb), z);
        e0  = expf(sbt-mx); e1 = expf(sbb-mx); ez = expf(z-mx);
        inv = 1.f / (e0 + e1 + 2.f*ez);
        float a_bt = e0*inv + off2;
        float a_bb = e1*inv + off2 + off;

        sc[gg][0]=a_tt; sc[gg][1]=a_tb; sc[gg][2]=a_bt; sc[gg][3]=a_bb;
        float det = a_tt*a_bb - a_tb*a_bt;
        sld[gg] = logf(fabsf(det)) * (float)(Pn*(Pn/2)*Cn);
    }
    __syncthreads();

    if (c == 0 && (blk & 1) == 0 && tid == 0) {
        if (OUT_ELEMS + b < out_size)
            out[OUT_ELEMS + b] = logdet_in[b] + sld[0] + sld[1];
    }

    float a_tt = sc[g][0], a_tb = sc[g][1], a_bt = sc[g][2], a_bb = sc[g][3];

    float4 ot, ob;
    if (g == 0) {  // pass-through at even lane (x,z)
        ot.x = xt.x;                    ob.x = xb.x;
        ot.y = a_tt*xt.y + a_tb*xb.y;   ob.y = a_bt*xt.y + a_bb*xb.y;
        ot.z = xt.z;                    ob.z = xb.z;
        ot.w = a_tt*xt.w + a_tb*xb.w;   ob.w = a_bt*xt.w + a_bb*xb.w;
    } else {       // pass-through at odd lane (y,w)
        ot.x = a_tt*xt.x + a_tb*xb.x;   ob.x = a_bt*xt.x + a_bb*xb.x;
        ot.y = xt.y;                    ob.y = xb.y;
        ot.z = a_tt*xt.z + a_tb*xb.z;   ob.z = a_bt*xt.z + a_bb*xb.z;
        ot.w = xt.w;                    ob.w = xb.w;
    }
    __stwt((float4*)(out + base), ot);
    __stwt((float4*)(out + base + 32*Wn), ob);
}

// ---------------------------------------------------------------------------
extern "C" void kernel_launch(void* const* d_in, const int* in_sizes, int n_in,
                              void* d_out, int out_size) {
    const float* x      = (const float*)d_in[0];
    const float* logdet = (const float*)d_in[1];
    const float* Wq1    = (const float*)d_in[2];
    const float* Wq2    = (const float*)d_in[3];
    const float* Wq3    = (const float*)d_in[4];
    const float* Wk1    = (const float*)d_in[5];
    const float* Wk2    = (const float*)d_in[6];
    const float* Wk3    = (const float*)d_in[7];
    const float* off1   = (const float*)d_in[8];
    const float* off2   = (const float*)d_in[9];
    const float* off3   = (const float*)d_in[10];
    float* out = (float*)d_out;

    prep_kernel<<<9, 256>>>(Wq1, Wq2, Wq3, Wk1, Wk2, Wk3);
    score_kernel<<<1024, 256>>>(x);
    out_kernel<<<12288, 256>>>(x, logdet, off1, off2, off3, out, out_size);
}

// round 11
// speedup vs baseline: 1.1392x; 1.1392x over previous
#include <cuda_runtime.h>
#include <math.h>

#define Bn 128
#define Cn 48
#define Hn 64
#define Wn 64
#define Pn 32
#define OUT_ELEMS (Bn*Cn*Hn*Wn)

// Scratch (no allocations allowed)
__device__ unsigned long long g_M2[Cn*Cn];   // M duplicated (m,m) as f32x2
__device__ float4 g_Spart[1024];             // partials: idx = (b*2+g)*4 + kq
__device__ float  g_A[Bn*2*4];               // attn coeffs per (b,g)

#define FMA2(acc, mm, vv) asm("fma.rn.f32x2 %0, %1, %2, %0;" : "+l"(acc) : "l"(mm), "l"(vv))
#define PACK2(dst, lo, hi) asm("mov.b64 %0, {%1,%2};" : "=l"(dst) : "f"(lo), "f"(hi))
#define UNPACK2(lo, hi, src) asm("mov.b64 {%0,%1}, %2;" : "=f"(lo), "=f"(hi) : "l"(src))

// ---------------------------------------------------------------------------
// Kernel A: prep. 9 blocks x 256 threads. Staging is register-batched: all 54
// global loads issued back-to-back (MLP=54, one latency exposure), THEN stored
// to smem. (The old streaming loop serialized LDG->STS at ~600cyc each.)
// ---------------------------------------------------------------------------
__global__ __launch_bounds__(256) void prep_kernel(
        const float* __restrict__ Wq1, const float* __restrict__ Wq2,
        const float* __restrict__ Wq3, const float* __restrict__ Wk1,
        const float* __restrict__ Wk2, const float* __restrict__ Wk3) {
    __shared__ float sW[6][Cn*Cn];   // 55296 B

    const int tid = threadIdx.x;

    // 2304 floats per matrix / 256 threads = 9 per thread per matrix
    float r0[9], r1[9], r2[9], r3[9], r4[9], r5[9];
    #pragma unroll
    for (int k = 0; k < 9; ++k) r0[k] = Wq1[tid + k*256];
    #pragma unroll
    for (int k = 0; k < 9; ++k) r1[k] = Wk1[tid + k*256];
    #pragma unroll
    for (int k = 0; k < 9; ++k) r2[k] = Wq2[tid + k*256];
    #pragma unroll
    for (int k = 0; k < 9; ++k) r3[k] = Wk2[tid + k*256];
    #pragma unroll
    for (int k = 0; k < 9; ++k) r4[k] = Wq3[tid + k*256];
    #pragma unroll
    for (int k = 0; k < 9; ++k) r5[k] = Wk3[tid + k*256];
    #pragma unroll
    for (int k = 0; k < 9; ++k) {
        sW[0][tid + k*256] = r0[k];
        sW[1][tid + k*256] = r1[k];
        sW[2][tid + k*256] = r2[k];
        sW[3][tid + k*256] = r3[k];
        sW[4][tid + k*256] = r4[k];
        sW[5][tid + k*256] = r5[k];
    }
    __syncthreads();

    int w = blockIdx.x * 256 + tid;          // 0..2303
    int c = w / Cn, c2 = w % Cn;
    float s = 0.f;
    #pragma unroll
    for (int o = 0; o < Cn; ++o) {
        s += sW[0][o*Cn+c]*sW[1][o*Cn+c2]
           + sW[2][o*Cn+c]*sW[3][o*Cn+c2]
           + sW[4][o*Cn+c]*sW[5][o*Cn+c2];
    }
    s *= (1.0f / sqrtf((float)(Cn*Pn*Pn)));
    ((float2*)g_M2)[w] = make_float2(s, s);
}

// ---------------------------------------------------------------------------
// Kernel B: scores — EXACT R6 form (measured-good). Grid 1024:
// bid -> (b, g, k-quarter kq). Block 256 = 8 warps.
// ---------------------------------------------------------------------------
__global__ __launch_bounds__(256, 3) void score_kernel(const float* __restrict__ x) {
    __shared__ unsigned long long sV[Cn*128];   // 49152 B  [c][k]
    __shared__ unsigned long long sM2[Cn*Cn];   // 18432 B
    __shared__ float4 sred[8];

    const int bid = blockIdx.x;
    const int kq = bid & 3;            // k-quarter (8 y-rows)
    const int g  = (bid >> 2) & 1;     // column-parity group
    const int b  = bid >> 3;
    const int tid = threadIdx.x;

    for (int i = tid; i < Cn*Cn; i += 256) sM2[i] = g_M2[i];

    const float2* xb2 = (const float2*)(x + (size_t)b * Cn * Hn * Wn);

    for (int idx = tid; idx < Cn*128; idx += 256) {
        int c2 = idx >> 7;
        int k  = idx & 127;
        int yy = k >> 4;
        int xx = k & 15;
        int yt = kq*8 + yy;
        float2 a  = xb2[((size_t)c2*Hn + yt)*32      + g*16 + xx];
        float2 bb = xb2[((size_t)c2*Hn + yt + 32)*32 + g*16 + xx];
        unsigned long long pk;
        if (g == 0) PACK2(pk, a.x, bb.x);
        else        PACK2(pk, a.y, bb.y);
        sV[idx] = pk;
    }
    __syncthreads();

    const int ci = tid >> 5;           // warp id: M-row group
    const int kl = tid & 31;           // k lane

    unsigned long long acc[24];
    #pragma unroll
    for (int i = 0; i < 24; ++i) acc[i] = 0ULL;

    #pragma unroll
    for (int c2 = 0; c2 < Cn; ++c2) {
        unsigned long long v0 = sV[c2*128 + kl];
        unsigned long long v1 = sV[c2*128 + kl + 32];
        unsigned long long v2 = sV[c2*128 + kl + 64];
        unsigned long long v3 = sV[c2*128 + kl + 96];
        #pragma unroll
        for (int r = 0; r < 6; ++r) {
            unsigned long long m = sM2[(ci*6 + r)*Cn + c2];   // broadcast
            FMA2(acc[r*4    ], m, v0);
            FMA2(acc[r*4 + 1], m, v1);
            FMA2(acc[r*4 + 2], m, v2);
            FMA2(acc[r*4 + 3], m, v3);
        }
    }

    float p00 = 0.f, p01 = 0.f, p10 = 0.f, p11 = 0.f;
    #pragma unroll
    for (int r = 0; r < 6; ++r) {
        #pragma unroll
        for (int j = 0; j < 4; ++j) {
            float wt, wb, vt, vb;
            UNPACK2(wt, wb, acc[r*4 + j]);
            unsigned long long v = sV[(ci*6 + r)*128 + kl + j*32];
            UNPACK2(vt, vb, v);
            p00 = fmaf(vt, wt, p00);  p01 = fmaf(vt, wb, p01);
            p10 = fmaf(vb, wt, p10);  p11 = fmaf(vb, wb, p11);
        }
    }

    #pragma unroll
    for (int off = 16; off; off >>= 1) {
        p00 += __shfl_xor_sync(0xffffffffu, p00, off);
        p01 += __shfl_xor_sync(0xffffffffu, p01, off);
        p10 += __shfl_xor_sync(0xffffffffu, p10, off);
        p11 += __shfl_xor_sync(0xffffffffu, p11, off);
    }
    if (kl == 0) sred[ci] = make_float4(p00, p01, p10, p11);
    __syncthreads();
    if (tid == 0) {
        float4 sv = sred[0];
        #pragma unroll
        for (int w = 1; w < 8; ++w) {
            float4 t = sred[w];
            sv.x += t.x; sv.y += t.y; sv.z += t.z; sv.w += t.w;
        }
        g_Spart[(b*2+g)*4 + kq] = sv;
    }
}

// ---------------------------------------------------------------------------
// Kernel C: softmax coeffs + logdet (separate, as in measured-best R9).
// ---------------------------------------------------------------------------
__global__ void attn_kernel(const float* __restrict__ logdet_in,
                            const float* __restrict__ off1p,
                            const float* __restrict__ off2p,
                            const float* __restrict__ off3p,
                            float* __restrict__ out, int out_size) {
    int b = threadIdx.x;
    if (b >= Bn) return;
    const float off  = off1p[0];
    const float off2 = off2p[0];
    const float off3 = off3p[0];
    float ld = logdet_in[b];

    #pragma unroll
    for (int g = 0; g < 2; ++g) {
        float4 s = g_Spart[(b*2+g)*4 + 0];
        #pragma unroll
        for (int qq = 1; qq < 4; ++qq) {
            float4 t = g_Spart[(b*2+g)*4 + qq];
            s.x += t.x; s.y += t.y; s.z += t.z; s.w += t.w;
        }
        float stt = s.x + off3, stb = s.y + off3;
        float sbt = s.z + off3, sbb = s.w + off3;
        float z = off3;

        float mx   = fmaxf(fmaxf(stt, stb), z);
        float e0   = expf(stt-mx), e1 = expf(stb-mx), ez = expf(z-mx);
        float inv  = 1.f / (e0 + e1 + 2.f*ez);
        float a_tt = e0*inv + off2 + off;
        float a_tb = e1*inv + off2;

        mx  = fmaxf(fmaxf(sbt, sbb), z);
        e0  = expf(sbt-mx); e1 = expf(sbb-mx); ez = expf(z-mx);
        inv = 1.f / (e0 + e1 + 2.f*ez);
        float a_bt = e0*inv + off2;
        float a_bb = e1*inv + off2 + off;

        float det = a_tt*a_bb - a_tb*a_bt;
        ld += logf(fabsf(det)) * (float)(Pn*(Pn/2)*Cn);

        float* a = &g_A[(b*2+g)*4];
        a[0]=a_tt; a[1]=a_tb; a[2]=a_bt; a[3]=a_bb;
    }
    if (OUT_ELEMS + b < out_size) out[OUT_ELEMS + b] = ld;
}

// ---------------------------------------------------------------------------
// Kernel D: output assembly (exact R9 form: __stwt + reversed batch order).
// ---------------------------------------------------------------------------
__global__ __launch_bounds__(256) void out_kernel(const float* __restrict__ x,
                                                  float* __restrict__ out) {
    int t  = blockIdx.x * blockDim.x + threadIdx.x;
    int x4 = t & 15;
    int y  = (t >> 4) & 31;
    int r  = t >> 9;
    int c  = r % Cn;
    int b  = Bn - 1 - (r / Cn);        // reversed batch order
    int g  = x4 >> 3;

    const float* A = &g_A[(b*2+g)*4];
    float a_tt = __ldg(&A[0]), a_tb = __ldg(&A[1]);
    float a_bt = __ldg(&A[2]), a_bb = __ldg(&A[3]);

    size_t base = (((size_t)b*Cn + c)*Hn + y)*Wn + x4*4;
    float4 xt = *(const float4*)(x + base);
    float4 xb = *(const float4*)(x + base + 32*Wn);
    float4 ot, ob;
    if (g == 0) {  // pass-through at even lane (x,z)
        ot.x = xt.x;                    ob.x = xb.x;
        ot.y = a_tt*xt.y + a_tb*xb.y;   ob.y = a_bt*xt.y + a_bb*xb.y;
        ot.z = xt.z;                    ob.z = xb.z;
        ot.w = a_tt*xt.w + a_tb*xb.w;   ob.w = a_bt*xt.w + a_bb*xb.w;
    } else {       // pass-through at odd lane (y,w)
        ot.x = a_tt*xt.x + a_tb*xb.x;   ob.x = a_bt*xt.x + a_bb*xb.x;
        ot.y = xt.y;                    ob.y = xb.y;
        ot.z = a_tt*xt.z + a_tb*xb.z;   ob.z = a_bt*xt.z + a_bb*xb.z;
        ot.w = xt.w;                    ob.w = xb.w;
    }
    __stwt((float4*)(out + base), ot);
    __stwt((float4*)(out + base + 32*Wn), ob);
}

// ---------------------------------------------------------------------------
extern "C" void kernel_launch(void* const* d_in, const int* in_sizes, int n_in,
                              void* d_out, int out_size) {
    const float* x      = (const float*)d_in[0];
    const float* logdet = (const float*)d_in[1];
    const float* Wq1    = (const float*)d_in[2];
    const float* Wq2    = (const float*)d_in[3];
    const float* Wq3    = (const float*)d_in[4];
    const float* Wk1    = (const float*)d_in[5];
    const float* Wk2    = (const float*)d_in[6];
    const float* Wk3    = (const float*)d_in[7];
    const float* off1   = (const float*)d_in[8];
    const float* off2   = (const float*)d_in[9];
    const float* off3   = (const float*)d_in[10];
    float* out = (float*)d_out;

    prep_kernel<<<9, 256>>>(Wq1, Wq2, Wq3, Wk1, Wk2, Wk3);
    score_kernel<<<1024, 256>>>(x);
    attn_kernel<<<1, 128>>>(logdet, off1, off2, off3, out, out_size);
    out_kernel<<<12288, 256>>>(x, out);
}

// round 12
// speedup vs baseline: 1.1843x; 1.0395x over previous
#include <cuda_runtime.h>
#include <math.h>

#define Bn 128
#define Cn 48
#define Hn 64
#define Wn 64
#define Pn 32
#define OUT_ELEMS (Bn*Cn*Hn*Wn)

// Scratch (no allocations allowed)
__device__ unsigned long long g_M2[Cn*Cn];   // M duplicated (m,m) as f32x2
__device__ float4 g_Spart[1024];             // partials: idx = (b*2+g)*4 + kq
__device__ float  g_A[Bn*2*4];               // attn coeffs per (b,g)

#define FMA2(acc, mm, vv) asm("fma.rn.f32x2 %0, %1, %2, %0;" : "+l"(acc) : "l"(mm), "l"(vv))
#define PACK2(dst, lo, hi) asm("mov.b64 %0, {%1,%2};" : "=l"(dst) : "f"(lo), "f"(hi))
#define UNPACK2(lo, hi, src) asm("mov.b64 {%0,%1}, %2;" : "=f"(lo), "=f"(hi) : "l"(src))

// ---------------------------------------------------------------------------
// Kernel A: prep. 9 blocks x 256 threads, register-batched staging (R11).
// ---------------------------------------------------------------------------
__global__ __launch_bounds__(256) void prep_kernel(
        const float* __restrict__ Wq1, const float* __restrict__ Wq2,
        const float* __restrict__ Wq3, const float* __restrict__ Wk1,
        const float* __restrict__ Wk2, const float* __restrict__ Wk3) {
    __shared__ float sW[6][Cn*Cn];   // 55296 B

    const int tid = threadIdx.x;

    float r0[9], r1[9], r2[9], r3[9], r4[9], r5[9];
    #pragma unroll
    for (int k = 0; k < 9; ++k) r0[k] = Wq1[tid + k*256];
    #pragma unroll
    for (int k = 0; k < 9; ++k) r1[k] = Wk1[tid + k*256];
    #pragma unroll
    for (int k = 0; k < 9; ++k) r2[k] = Wq2[tid + k*256];
    #pragma unroll
    for (int k = 0; k < 9; ++k) r3[k] = Wk2[tid + k*256];
    #pragma unroll
    for (int k = 0; k < 9; ++k) r4[k] = Wq3[tid + k*256];
    #pragma unroll
    for (int k = 0; k < 9; ++k) r5[k] = Wk3[tid + k*256];
    #pragma unroll
    for (int k = 0; k < 9; ++k) {
        sW[0][tid + k*256] = r0[k];
        sW[1][tid + k*256] = r1[k];
        sW[2][tid + k*256] = r2[k];
        sW[3][tid + k*256] = r3[k];
        sW[4][tid + k*256] = r4[k];
        sW[5][tid + k*256] = r5[k];
    }
    __syncthreads();

    int w = blockIdx.x * 256 + tid;          // 0..2303
    int c = w / Cn, c2 = w % Cn;
    float s = 0.f;
    #pragma unroll
    for (int o = 0; o < Cn; ++o) {
        s += sW[0][o*Cn+c]*sW[1][o*Cn+c2]
           + sW[2][o*Cn+c]*sW[3][o*Cn+c2]
           + sW[4][o*Cn+c]*sW[5][o*Cn+c2];
    }
    s *= (1.0f / sqrtf((float)(Cn*Pn*Pn)));
    ((float2*)g_M2)[w] = make_float2(s, s);
}

// ---------------------------------------------------------------------------
// Kernel B: scores. R6 mainloop (measured-good), staging register-batched:
// M: 9 independent LDG.64 then 9 STS; V: 2 batches of 12 (24 LDG.64 in
// flight), so staging costs ~2 latency exposures instead of 33 serialized.
// ---------------------------------------------------------------------------
__global__ __launch_bounds__(256, 3) void score_kernel(const float* __restrict__ x) {
    __shared__ unsigned long long sV[Cn*128];   // 49152 B  [c][k]
    __shared__ unsigned long long sM2[Cn*Cn];   // 18432 B
    __shared__ float4 sred[8];

    const int bid = blockIdx.x;
    const int kq = bid & 3;            // k-quarter (8 y-rows)
    const int g  = (bid >> 2) & 1;     // column-parity group
    const int b  = bid >> 3;
    const int tid = threadIdx.x;

    // --- M staging: batched (9 loads in flight, then 9 stores) ---
    {
        unsigned long long m[9];
        #pragma unroll
        for (int k = 0; k < 9; ++k) m[k] = g_M2[tid + k*256];
        #pragma unroll
        for (int k = 0; k < 9; ++k) sM2[tid + k*256] = m[k];
    }

    const float2* xb2 = (const float2*)(x + (size_t)b * Cn * Hn * Wn);

    // --- V staging: 24 entries/thread in 2 batches of 12 ---
    // entry idx = tid + k*256 : c2 = idx>>7, kk = idx&127, yy = kk>>4, xx = kk&15
    #pragma unroll
    for (int half = 0; half < 2; ++half) {
        float2 ra[12], rb[12];
        #pragma unroll
        for (int k = 0; k < 12; ++k) {
            int idx = tid + (half*12 + k)*256;
            int c2 = idx >> 7;
            int kk = idx & 127;
            int yy = kk >> 4;
            int xx = kk & 15;
            int yt = kq*8 + yy;
            ra[k] = xb2[((size_t)c2*Hn + yt)*32      + g*16 + xx];
            rb[k] = xb2[((size_t)c2*Hn + yt + 32)*32 + g*16 + xx];
        }
        #pragma unroll
        for (int k = 0; k < 12; ++k) {
            int idx = tid + (half*12 + k)*256;
            unsigned long long pk;
            if (g == 0) PACK2(pk, ra[k].x, rb[k].x);
            else        PACK2(pk, ra[k].y, rb[k].y);
            sV[idx] = pk;
        }
    }
    __syncthreads();

    const int ci = tid >> 5;           // warp id: M-row group
    const int kl = tid & 31;           // k lane

    unsigned long long acc[24];
    #pragma unroll
    for (int i = 0; i < 24; ++i) acc[i] = 0ULL;

    #pragma unroll
    for (int c2 = 0; c2 < Cn; ++c2) {
        unsigned long long v0 = sV[c2*128 + kl];
        unsigned long long v1 = sV[c2*128 + kl + 32];
        unsigned long long v2 = sV[c2*128 + kl + 64];
        unsigned long long v3 = sV[c2*128 + kl + 96];
        #pragma unroll
        for (int r = 0; r < 6; ++r) {
            unsigned long long m = sM2[(ci*6 + r)*Cn + c2];   // broadcast
            FMA2(acc[r*4    ], m, v0);
            FMA2(acc[r*4 + 1], m, v1);
            FMA2(acc[r*4 + 2], m, v2);
            FMA2(acc[r*4 + 3], m, v3);
        }
    }

    float p00 = 0.f, p01 = 0.f, p10 = 0.f, p11 = 0.f;
    #pragma unroll
    for (int r = 0; r < 6; ++r) {
        #pragma unroll
        for (int j = 0; j < 4; ++j) {
            float wt, wb, vt, vb;
            UNPACK2(wt, wb, acc[r*4 + j]);
            unsigned long long v = sV[(ci*6 + r)*128 + kl + j*32];
            UNPACK2(vt, vb, v);
            p00 = fmaf(vt, wt, p00);  p01 = fmaf(vt, wb, p01);
            p10 = fmaf(vb, wt, p10);  p11 = fmaf(vb, wb, p11);
        }
    }

    #pragma unroll
    for (int off = 16; off; off >>= 1) {
        p00 += __shfl_xor_sync(0xffffffffu, p00, off);
        p01 += __shfl_xor_sync(0xffffffffu, p01, off);
        p10 += __shfl_xor_sync(0xffffffffu, p10, off);
        p11 += __shfl_xor_sync(0xffffffffu, p11, off);
    }
    if (kl == 0) sred[ci] = make_float4(p00, p01, p10, p11);
    __syncthreads();
    if (tid == 0) {
        float4 sv = sred[0];
        #pragma unroll
        for (int w = 1; w < 8; ++w) {
            float4 t = sred[w];
            sv.x += t.x; sv.y += t.y; sv.z += t.z; sv.w += t.w;
        }
        g_Spart[(b*2+g)*4 + kq] = sv;
    }
}

// ---------------------------------------------------------------------------
// Kernel C: softmax coeffs + logdet.
// ---------------------------------------------------------------------------
__global__ void attn_kernel(const float* __restrict__ logdet_in,
                            const float* __restrict__ off1p,
                            const float* __restrict__ off2p,
                            const float* __restrict__ off3p,
                            float* __restrict__ out, int out_size) {
    int b = threadIdx.x;
    if (b >= Bn) return;
    const float off  = off1p[0];
    const float off2 = off2p[0];
    const float off3 = off3p[0];
    float ld = logdet_in[b];

    #pragma unroll
    for (int g = 0; g < 2; ++g) {
        float4 s = g_Spart[(b*2+g)*4 + 0];
        #pragma unroll
        for (int qq = 1; qq < 4; ++qq) {
            float4 t = g_Spart[(b*2+g)*4 + qq];
            s.x += t.x; s.y += t.y; s.z += t.z; s.w += t.w;
        }
        float stt = s.x + off3, stb = s.y + off3;
        float sbt = s.z + off3, sbb = s.w + off3;
        float z = off3;

        float mx   = fmaxf(fmaxf(stt, stb), z);
        float e0   = expf(stt-mx), e1 = expf(stb-mx), ez = expf(z-mx);
        float inv  = 1.f / (e0 + e1 + 2.f*ez);
        float a_tt = e0*inv + off2 + off;
        float a_tb = e1*inv + off2;

        mx  = fmaxf(fmaxf(sbt, sbb), z);
        e0  = expf(sbt-mx); e1 = expf(sbb-mx); ez = expf(z-mx);
        inv = 1.f / (e0 + e1 + 2.f*ez);
        float a_bt = e0*inv + off2;
        float a_bb = e1*inv + off2 + off;

        float det = a_tt*a_bb - a_tb*a_bt;
        ld += logf(fabsf(det)) * (float)(Pn*(Pn/2)*Cn);

        float* a = &g_A[(b*2+g)*4];
        a[0]=a_tt; a[1]=a_tb; a[2]=a_bt; a[3]=a_bb;
    }
    if (OUT_ELEMS + b < out_size) out[OUT_ELEMS + b] = ld;
}

// ---------------------------------------------------------------------------
// Kernel D: output assembly (exact R9/R11 form: __stwt + reversed batch order).
// ---------------------------------------------------------------------------
__global__ __launch_bounds__(256) void out_kernel(const float* __restrict__ x,
                                                  float* __restrict__ out) {
    int t  = blockIdx.x * blockDim.x + threadIdx.x;
    int x4 = t & 15;
    int y  = (t >> 4) & 31;
    int r  = t >> 9;
    int c  = r % Cn;
    int b  = Bn - 1 - (r / Cn);        // reversed batch order
    int g  = x4 >> 3;

    const float* A = &g_A[(b*2+g)*4];
    float a_tt = __ldg(&A[0]), a_tb = __ldg(&A[1]);
    float a_bt = __ldg(&A[2]), a_bb = __ldg(&A[3]);

    size_t base = (((size_t)b*Cn + c)*Hn + y)*Wn + x4*4;
    float4 xt = *(const float4*)(x + base);
    float4 xb = *(const float4*)(x + base + 32*Wn);
    float4 ot, ob;
    if (g == 0) {  // pass-through at even lane (x,z)
        ot.x = xt.x;                    ob.x = xb.x;
        ot.y = a_tt*xt.y + a_tb*xb.y;   ob.y = a_bt*xt.y + a_bb*xb.y;
        ot.z = xt.z;                    ob.z = xb.z;
        ot.w = a_tt*xt.w + a_tb*xb.w;   ob.w = a_bt*xt.w + a_bb*xb.w;
    } else {       // pass-through at odd lane (y,w)
        ot.x = a_tt*xt.x + a_tb*xb.x;   ob.x = a_bt*xt.x + a_bb*xb.x;
        ot.y = xt.y;                    ob.y = xb.y;
        ot.z = a_tt*xt.z + a_tb*xb.z;   ob.z = a_bt*xt.z + a_bb*xb.z;
        ot.w = xt.w;                    ob.w = xb.w;
    }
    __stwt((float4*)(out + base), ot);
    __stwt((float4*)(out + base + 32*Wn), ob);
}

// ---------------------------------------------------------------------------
extern "C" void kernel_launch(void* const* d_in, const int* in_sizes, int n_in,
                              void* d_out, int out_size) {
    const float* x      = (const float*)d_in[0];
    const float* logdet = (const float*)d_in[1];
    const float* Wq1    = (const float*)d_in[2];
    const float* Wq2    = (const float*)d_in[3];
    const float* Wq3    = (const float*)d_in[4];
    const float* Wk1    = (const float*)d_in[5];
    const float* Wk2    = (const float*)d_in[6];
    const float* Wk3    = (const float*)d_in[7];
    const float* off1   = (const float*)d_in[8];
    const float* off2   = (const float*)d_in[9];
    const float* off3   = (const float*)d_in[10];
    float* out = (float*)d_out;

    prep_kernel<<<9, 256>>>(Wq1, Wq2, Wq3, Wk1, Wk2, Wk3);
    score_kernel<<<1024, 256>>>(x);
    attn_kernel<<<1, 128>>>(logdet, off1, off2, off3, out, out_size);
    out_kernel<<<12288, 256>>>(x, out);
}

// round 13
// speedup vs baseline: 1.2494x; 1.0550x over previous
#include <cuda_runtime.h>
#include <math.h>

#define Bn 128
#define Cn 48
#define Hn 64
#define Wn 64
#define Pn 32
#define OUT_ELEMS (Bn*Cn*Hn*Wn)

// Scratch (no allocations allowed)
__device__ unsigned long long g_M2[Cn*Cn];   // M duplicated (m,m) as f32x2
__device__ float4 g_S[256];                  // raw score sums per (b*2+g)

#define FMA2(acc, mm, vv) asm("fma.rn.f32x2 %0, %1, %2, %0;" : "+l"(acc) : "l"(mm), "l"(vv))
#define PACK2(dst, lo, hi) asm("mov.b64 %0, {%1,%2};" : "=l"(dst) : "f"(lo), "f"(hi))
#define UNPACK2(lo, hi, src) asm("mov.b64 {%0,%1}, %2;" : "=f"(lo), "=f"(hi) : "l"(src))

// ---------------------------------------------------------------------------
// Kernel A: prep (R11 measured-good form, register-batched staging).
// ---------------------------------------------------------------------------
__global__ __launch_bounds__(256) void prep_kernel(
        const float* __restrict__ Wq1, const float* __restrict__ Wq2,
        const float* __restrict__ Wq3, const float* __restrict__ Wk1,
        const float* __restrict__ Wk2, const float* __restrict__ Wk3) {
    __shared__ float sW[6][Cn*Cn];   // 55296 B

    const int tid = threadIdx.x;

    float r0[9], r1[9], r2[9], r3[9], r4[9], r5[9];
    #pragma unroll
    for (int k = 0; k < 9; ++k) r0[k] = Wq1[tid + k*256];
    #pragma unroll
    for (int k = 0; k < 9; ++k) r1[k] = Wk1[tid + k*256];
    #pragma unroll
    for (int k = 0; k < 9; ++k) r2[k] = Wq2[tid + k*256];
    #pragma unroll
    for (int k = 0; k < 9; ++k) r3[k] = Wk2[tid + k*256];
    #pragma unroll
    for (int k = 0; k < 9; ++k) r4[k] = Wq3[tid + k*256];
    #pragma unroll
    for (int k = 0; k < 9; ++k) r5[k] = Wk3[tid + k*256];
    #pragma unroll
    for (int k = 0; k < 9; ++k) {
        sW[0][tid + k*256] = r0[k];
        sW[1][tid + k*256] = r1[k];
        sW[2][tid + k*256] = r2[k];
        sW[3][tid + k*256] = r3[k];
        sW[4][tid + k*256] = r4[k];
        sW[5][tid + k*256] = r5[k];
    }
    __syncthreads();

    int w = blockIdx.x * 256 + tid;          // 0..2303
    int c = w / Cn, c2 = w % Cn;
    float s = 0.f;
    #pragma unroll
    for (int o = 0; o < Cn; ++o) {
        s += sW[0][o*Cn+c]*sW[1][o*Cn+c2]
           + sW[2][o*Cn+c]*sW[3][o*Cn+c2]
           + sW[4][o*Cn+c]*sW[5][o*Cn+c2];
    }
    s *= (1.0f / sqrtf((float)(Cn*Pn*Pn)));
    ((float2*)g_M2)[w] = make_float2(s, s);
}

// ---------------------------------------------------------------------------
// Kernel B: FUSED score + softmax + output. 256 CTAs x 256 threads.
// CTA = (b, g). Phase 1: R12 score mainloop over 4 kq chunks -> raw score
// sums (also stored to g_S for the logdet kernel) -> local softmax coeffs.
// Phase 2: output assembly for (b, column-block g); x lines are L2-hot from
// phase 1 (score's float2 loads fetch full 128B rows), __stwt writes.
// ---------------------------------------------------------------------------
__global__ __launch_bounds__(256, 2) void fused_kernel(
        const float* __restrict__ x,
        const float* __restrict__ off1p, const float* __restrict__ off2p,
        const float* __restrict__ off3p,
        float* __restrict__ out) {
    __shared__ unsigned long long sV[Cn*128];   // 49152 B  [c][k]
    __shared__ unsigned long long sM2[Cn*Cn];   // 18432 B
    __shared__ float4 sred[8];
    __shared__ float sc[4];

    const int bid = blockIdx.x;
    const int g = bid & 1;
    const int b = bid >> 1;
    const int tid = threadIdx.x;
    const int ci = tid >> 5;
    const int kl = tid & 31;

    // M staging: batched (9 loads in flight, then 9 stores)
    {
        unsigned long long m[9];
        #pragma unroll
        for (int k = 0; k < 9; ++k) m[k] = g_M2[tid + k*256];
        #pragma unroll
        for (int k = 0; k < 9; ++k) sM2[tid + k*256] = m[k];
    }

    const float2* xb2 = (const float2*)(x + (size_t)b * Cn * Hn * Wn);

    float p00 = 0.f, p01 = 0.f, p10 = 0.f, p11 = 0.f;

    for (int kq = 0; kq < 4; ++kq) {
        __syncthreads();   // previous epilogue readers done before sV overwrite
        // V staging: 24 entries/thread in 3 batches of 8 (keeps regs < cap)
        #pragma unroll
        for (int bt = 0; bt < 3; ++bt) {
            float2 ra[8], rb[8];
            #pragma unroll
            for (int k = 0; k < 8; ++k) {
                int idx = tid + (bt*8 + k)*256;
                int c2 = idx >> 7;
                int kk = idx & 127;
                int yy = kk >> 4;
                int xx = kk & 15;
                int yt = kq*8 + yy;
                ra[k] = xb2[((size_t)c2*Hn + yt)*32      + g*16 + xx];
                rb[k] = xb2[((size_t)c2*Hn + yt + 32)*32 + g*16 + xx];
            }
            #pragma unroll
            for (int k = 0; k < 8; ++k) {
                int idx = tid + (bt*8 + k)*256;
                unsigned long long pk;
                if (g == 0) PACK2(pk, ra[k].x, rb[k].x);
                else        PACK2(pk, ra[k].y, rb[k].y);
                sV[idx] = pk;
            }
        }
        __syncthreads();

        unsigned long long acc[24];
        #pragma unroll
        for (int i = 0; i < 24; ++i) acc[i] = 0ULL;

        #pragma unroll
        for (int c2 = 0; c2 < Cn; ++c2) {
            unsigned long long v0 = sV[c2*128 + kl];
            unsigned long long v1 = sV[c2*128 + kl + 32];
            unsigned long long v2 = sV[c2*128 + kl + 64];
            unsigned long long v3 = sV[c2*128 + kl + 96];
            #pragma unroll
            for (int r = 0; r < 6; ++r) {
                unsigned long long m = sM2[(ci*6 + r)*Cn + c2];   // broadcast
                FMA2(acc[r*4    ], m, v0);
                FMA2(acc[r*4 + 1], m, v1);
                FMA2(acc[r*4 + 2], m, v2);
                FMA2(acc[r*4 + 3], m, v3);
            }
        }

        #pragma unroll
        for (int r = 0; r < 6; ++r) {
            #pragma unroll
            for (int j = 0; j < 4; ++j) {
                float wt, wb, vt, vb;
                UNPACK2(wt, wb, acc[r*4 + j]);
                unsigned long long v = sV[(ci*6 + r)*128 + kl + j*32];
                UNPACK2(vt, vb, v);
                p00 = fmaf(vt, wt, p00);  p01 = fmaf(vt, wb, p01);
                p10 = fmaf(vb, wt, p10);  p11 = fmaf(vb, wb, p11);
            }
        }
    }

    // reduce p across the block (deterministic)
    #pragma unroll
    for (int off = 16; off; off >>= 1) {
        p00 += __shfl_xor_sync(0xffffffffu, p00, off);
        p01 += __shfl_xor_sync(0xffffffffu, p01, off);
        p10 += __shfl_xor_sync(0xffffffffu, p10, off);
        p11 += __shfl_xor_sync(0xffffffffu, p11, off);
    }
    if (kl == 0) sred[ci] = make_float4(p00, p01, p10, p11);
    __syncthreads();
    if (tid == 0) {
        float4 sv = sred[0];
        #pragma unroll
        for (int w = 1; w < 8; ++w) {
            float4 t = sred[w];
            sv.x += t.x; sv.y += t.y; sv.z += t.z; sv.w += t.w;
        }
        g_S[bid] = sv;                       // raw sums for the logdet kernel

        const float off  = off1p[0];
        const float off2 = off2p[0];
        const float off3 = off3p[0];
        float stt = sv.x + off3, stb = sv.y + off3;
        float sbt = sv.z + off3, sbb = sv.w + off3;
        float z = off3;

        float mx  = fmaxf(fmaxf(stt, stb), z);
        float e0  = expf(stt-mx), e1 = expf(stb-mx), ez = expf(z-mx);
        float inv = 1.f / (e0 + e1 + 2.f*ez);
        sc[0] = e0*inv + off2 + off;         // a_tt
        sc[1] = e1*inv + off2;               // a_tb

        mx  = fmaxf(fmaxf(sbt, sbb), z);
        e0  = expf(sbt-mx); e1 = expf(sbb-mx); ez = expf(z-mx);
        inv = 1.f / (e0 + e1 + 2.f*ez);
        sc[2] = e0*inv + off2;               // a_bt
        sc[3] = e1*inv + off2 + off;         // a_bb
    }
    __syncthreads();

    // ---- Phase 2: output for (b, column-block g) ----
    const float a_tt = sc[0], a_tb = sc[1], a_bt = sc[2], a_bb = sc[3];
    const float4* xp = (const float4*)(x + (size_t)b * Cn * Hn * Wn);
    float4* op = (float4*)(out + (size_t)b * Cn * Hn * Wn);

    #pragma unroll 4
    for (int i = 0; i < 48; ++i) {
        int idx = tid + i*256;               // 12288 float4-pairs
        int x4l = idx & 7;
        int y   = (idx >> 3) & 31;
        int c   = idx >> 8;
        int fo  = (c*Hn + y)*16 + g*8 + x4l; // float4 offset
        float4 xt = xp[fo];
        float4 xb = xp[fo + 32*16];
        float4 ot, ob;
        if (g == 0) {  // pass-through at even columns (x,z)
            ot.x = xt.x;                    ob.x = xb.x;
            ot.y = a_tt*xt.y + a_tb*xb.y;   ob.y = a_bt*xt.y + a_bb*xb.y;
            ot.z = xt.z;                    ob.z = xb.z;
            ot.w = a_tt*xt.w + a_tb*xb.w;   ob.w = a_bt*xt.w + a_bb*xb.w;
        } else {       // pass-through at odd columns (y,w)
            ot.x = a_tt*xt.x + a_tb*xb.x;   ob.x = a_bt*xt.x + a_bb*xb.x;
            ot.y = xt.y;                    ob.y = xb.y;
            ot.z = a_tt*xt.z + a_tb*xb.z;   ob.z = a_bt*xt.z + a_bb*xb.z;
            ot.w = xt.w;                    ob.w = xb.w;
        }
        __stwt(&op[fo], ot);
        __stwt(&op[fo + 32*16], ob);
    }
}

// ---------------------------------------------------------------------------
// Kernel C: logdet from raw score sums (needs both g of each b).
// ---------------------------------------------------------------------------
__global__ void logdet_kernel(const float* __restrict__ logdet_in,
                              const float* __restrict__ off1p,
                              const float* __restrict__ off2p,
                              const float* __restrict__ off3p,
                              float* __restrict__ out, int out_size) {
    int b = threadIdx.x;
    if (b >= Bn) return;
    const float off  = off1p[0];
    const float off2 = off2p[0];
    const float off3 = off3p[0];
    float ld = logdet_in[b];

    #pragma unroll
    for (int g = 0; g < 2; ++g) {
        float4 s = g_S[b*2 + g];
        float stt = s.x + off3, stb = s.y + off3;
        float sbt = s.z + off3, sbb = s.w + off3;
        float z = off3;

        float mx   = fmaxf(fmaxf(stt, stb), z);
        float e0   = expf(stt-mx), e1 = expf(stb-mx), ez = expf(z-mx);
        float inv  = 1.f / (e0 + e1 + 2.f*ez);
        float a_tt = e0*inv + off2 + off;
        float a_tb = e1*inv + off2;

        mx  = fmaxf(fmaxf(sbt, sbb), z);
        e0  = expf(sbt-mx); e1 = expf(sbb-mx); ez = expf(z-mx);
        inv = 1.f / (e0 + e1 + 2.f*ez);
        float a_bt = e0*inv + off2;
        float a_bb = e1*inv + off2 + off;

        float det = a_tt*a_bb - a_tb*a_bt;
        ld += logf(fabsf(det)) * (float)(Pn*(Pn/2)*Cn);
    }
    if (OUT_ELEMS + b < out_size) out[OUT_ELEMS + b] = ld;
}

// ---------------------------------------------------------------------------
extern "C" void kernel_launch(void* const* d_in, const int* in_sizes, int n_in,
                              void* d_out, int out_size) {
    const float* x      = (const float*)d_in[0];
    const float* logdet = (const float*)d_in[1];
    const float* Wq1    = (const float*)d_in[2];
    const float* Wq2    = (const float*)d_in[3];
    const float* Wq3    = (const float*)d_in[4];
    const float* Wk1    = (const float*)d_in[5];
    const float* Wk2    = (const float*)d_in[6];
    const float* Wk3    = (const float*)d_in[7];
    const float* off1   = (const float*)d_in[8];
    const float* off2   = (const float*)d_in[9];
    const float* off3   = (const float*)d_in[10];
    float* out = (float*)d_out;

    prep_kernel<<<9, 256>>>(Wq1, Wq2, Wq3, Wk1, Wk2, Wk3);
    fused_kernel<<<256, 256>>>(x, off1, off2, off3, out);
    logdet_kernel<<<1, 128>>>(logdet, off1, off2, off3, out, out_size);
}